// round 16
// baseline (speedup 1.0000x reference)
#include <cuda_runtime.h>
#include <cuda_fp16.h>
#include <stdint.h>
#include <math.h>

#define ROWS   (8 * 4096)     // 32768
#define CH     2048
#define BM     256
#define BN     128
#define BK     64
#define CHUNKS (CH / BK)      // 32 per tile
#define NSTAGE 4
#define NT_N   (CH / BN)      // 16
#define NT_M   (ROWS / BM)    // 128
#define NTILES (NT_M * NT_N)  // 2048

// per stage: A [256][64] half (32KB) + W [128][64] half (16KB)
#define A_BYTES     (256 * 64 * 2)
#define W_BYTES     (128 * 64 * 2)
#define OFF_A       0
#define OFF_W       (A_BYTES)
#define STAGE_BYTES (A_BYTES + W_BYTES)      // 48KB
#define SMEM_TOTAL  (NSTAGE * STAGE_BYTES)   // 192KB

#define PRE_SMEM    (8 * 512 * 16)           // 64KB: 8 warps x 512 float4
#define LN2_SMEM    (8 * 256 * 16)           // 32KB: 8 warps x 256 uint4

// ---- scratch (__device__ globals; allocation-free rule) ----
__device__ __half g_act[(size_t)ROWS * CH];
__device__ __half g_h1 [(size_t)ROWS * CH];
__device__ __half g_w1t[(size_t)CH * CH];
__device__ __half g_w2t[(size_t)CH * CH];

// ======================= PTX helpers =======================
__device__ __forceinline__ uint32_t smem_u32(const void* p) {
    uint32_t a;
    asm("{ .reg .u64 t; cvta.to.shared.u64 t, %1; cvt.u32.u64 %0, t; }" : "=r"(a) : "l"(p));
    return a;
}

__device__ __forceinline__ void cp16(uint32_t s, const void* g) {
    asm volatile("cp.async.cg.shared.global [%0], [%1], 16;" :: "r"(s), "l"(g));
}

#define CP_COMMIT()   asm volatile("cp.async.commit_group;" ::: "memory")
#define CP_WAIT(n)    asm volatile("cp.async.wait_group %0;" :: "n"(n) : "memory")

#define LDSM4(r, addr) \
    asm volatile("ldmatrix.sync.aligned.m8n8.x4.shared.b16 {%0,%1,%2,%3}, [%4];" \
        : "=r"((r)[0]), "=r"((r)[1]), "=r"((r)[2]), "=r"((r)[3]) : "r"(addr))

#define MMA16816(c, a, b) \
    asm volatile("mma.sync.aligned.m16n8k16.row.col.f32.f16.f16.f32 " \
        "{%0,%1,%2,%3}, {%4,%5,%6,%7}, {%8,%9}, {%0,%1,%2,%3};" \
        : "+f"((c)[0]), "+f"((c)[1]), "+f"((c)[2]), "+f"((c)[3]) \
        : "r"((a)[0]), "r"((a)[1]), "r"((a)[2]), "r"((a)[3]), "r"((b)[0]), "r"((b)[1]))

// swizzled smem byte offset for (row, 16B-chunk kc) in a [rows][64]half matrix
__device__ __forceinline__ uint32_t swz(int row, int kc) {
    return (uint32_t)(row * 128 + ((kc ^ (row & 7)) << 4));
}

__device__ __forceinline__ float2 warp_reduce_sum2(float a, float b) {
    #pragma unroll
    for (int off = 16; off > 0; off >>= 1) {
        a += __shfl_xor_sync(0xffffffffu, a, off);
        b += __shfl_xor_sync(0xffffffffu, b, off);
    }
    return make_float2(a, b);
}

// ======================= fused preprocessing =======================
// blocks [0, 4096):           transpose+convert w1 -> w1t
// blocks [4096, 8192):        transpose+convert w2 -> w2t
// blocks [8192, 8192+ROWS/8): LN+SiLU, warp-per-row (two-pass via smem), x -> act (fp16)
__global__ void __launch_bounds__(256) preprocess_kernel(
    const float* __restrict__ x,
    const float* __restrict__ w1,
    const float* __restrict__ w2,
    const float* __restrict__ gamma,
    const float* __restrict__ beta,
    __half* __restrict__ w1t,
    __half* __restrict__ w2t,
    __half* __restrict__ act)
{
    extern __shared__ char dynsm[];
    const int bid = blockIdx.x;
    const int tid = threadIdx.x;

    if (bid < 8192) {
        float (*t)[33] = (float(*)[33])dynsm;
        const float* w = (bid < 4096) ? w1 : w2;
        __half* wt     = (bid < 4096) ? w1t : w2t;
        const int b    = bid & 4095;
        const int n0   = (b & 63) * 32;
        const int k0   = (b >> 6) * 32;
        const int tx = tid & 31, ty = tid >> 5;
        for (int i = ty; i < 32; i += 8)
            t[i][tx] = w[(size_t)(k0 + i) * CH + n0 + tx];
        __syncthreads();
        for (int i = ty; i < 32; i += 8)
            wt[(size_t)(n0 + i) * CH + k0 + tx] = __float2half_rn(t[tx][i]);
        return;
    }

    // warp-per-row LN+SiLU, two-pass; pass-1 stages the row in warp-private smem
    const size_t row = (size_t)(bid - 8192) * 8 + (tid >> 5);
    const int lane = tid & 31;
    const float4* xr = (const float4*)(x + row * (size_t)CH);     // 512 float4 per row
    float4* sbuf = ((float4*)dynsm) + (size_t)(tid >> 5) * 512;   // warp-private 8KB

    // pass 1: stream + accumulate + stage to smem (no data kept in regs)
    float s = 0.f, sq = 0.f;
    #pragma unroll
    for (int i = 0; i < 16; i++) {
        float4 v = xr[lane + i * 32];
        sbuf[lane + i * 32] = v;
        s  += v.x + v.y + v.z + v.w;
        sq += v.x*v.x + v.y*v.y + v.z*v.z + v.w*v.w;
    }
    float2 r = warp_reduce_sum2(s, sq);
    const float inv_n = 1.0f / (float)CH;
    float mu  = r.x * inv_n;
    float var = r.y * inv_n - mu * mu;
    float inv = rsqrtf(var + 1e-6f);

    const float4* gr = (const float4*)gamma;
    const float4* br = (const float4*)beta;
    uint2* orow = (uint2*)(act + row * (size_t)CH);   // 512 uint2 per row
    #pragma unroll
    for (int i = 0; i < 16; i++) {
        const int c = lane + i * 32;
        float4 v = sbuf[c];                // smem readback (same thread wrote it)
        float4 g = gr[c], b = br[c];
        float y0 = (v.x - mu) * inv * g.x + b.x;
        float y1 = (v.y - mu) * inv * g.y + b.y;
        float y2 = (v.z - mu) * inv * g.z + b.z;
        float y3 = (v.w - mu) * inv * g.w + b.w;
        y0 *= 1.0f / (1.0f + __expf(-y0));
        y1 *= 1.0f / (1.0f + __expf(-y1));
        y2 *= 1.0f / (1.0f + __expf(-y2));
        y3 *= 1.0f / (1.0f + __expf(-y3));
        __half2 h0 = __float22half2_rn(make_float2(y0, y1));
        __half2 h1v = __float22half2_rn(make_float2(y2, y3));
        uint2 o;
        o.x = *(uint32_t*)&h0;
        o.y = *(uint32_t*)&h1v;
        orow[c] = o;
    }
}

// ======================= LN + SiLU (fp16 in, warp-per-row two-pass via smem) -> fp16 =======================
__global__ void __launch_bounds__(256) ln_silu_f16_kernel(
    const __half* __restrict__ x,
    const float* __restrict__ gamma,
    const float* __restrict__ beta,
    __half* __restrict__ o)
{
    extern __shared__ char dynsm[];
    const size_t row = (size_t)blockIdx.x * 8 + (threadIdx.x >> 5);
    const int lane = threadIdx.x & 31;
    const uint4* xr = (const uint4*)(x + row * (size_t)CH);       // 256 uint4 per row
    uint4* sbuf = ((uint4*)dynsm) + (size_t)(threadIdx.x >> 5) * 256;  // warp-private 4KB

    float s = 0.f, sq = 0.f;
    #pragma unroll
    for (int i = 0; i < 8; i++) {
        uint4 raw = xr[lane + i * 32];
        sbuf[lane + i * 32] = raw;
        const __half2* h = (const __half2*)&raw;
        #pragma unroll
        for (int j = 0; j < 4; j++) {
            float2 f = __half22float2(h[j]);
            s += f.x + f.y;
            sq += f.x*f.x + f.y*f.y;
        }
    }
    float2 r = warp_reduce_sum2(s, sq);
    const float inv_n = 1.0f / (float)CH;
    float mu  = r.x * inv_n;
    float var = r.y * inv_n - mu * mu;
    float inv = rsqrtf(var + 1e-6f);

    const float4* gr = (const float4*)gamma;
    const float4* br = (const float4*)beta;
    uint4* orow = (uint4*)(o + row * (size_t)CH);
    #pragma unroll
    for (int i = 0; i < 8; i++) {
        const int c = lane + i * 32;         // uint4 index; covers elems 8c..8c+7
        uint4 raw = sbuf[c];                 // smem readback
        const __half2* h = (const __half2*)&raw;
        uint4 out;
        __half2* oh = (__half2*)&out;
        #pragma unroll
        for (int j = 0; j < 2; j++) {
            float4 g = gr[2*c + j], b = br[2*c + j];
            float2 f0 = __half22float2(h[2*j]);
            float2 f1 = __half22float2(h[2*j + 1]);
            float y0 = (f0.x - mu) * inv * g.x + b.x;
            float y1 = (f0.y - mu) * inv * g.y + b.y;
            float y2 = (f1.x - mu) * inv * g.z + b.z;
            float y3 = (f1.y - mu) * inv * g.w + b.w;
            y0 *= 1.0f / (1.0f + __expf(-y0));
            y1 *= 1.0f / (1.0f + __expf(-y1));
            y2 *= 1.0f / (1.0f + __expf(-y2));
            y3 *= 1.0f / (1.0f + __expf(-y3));
            oh[2*j]     = __float22half2_rn(make_float2(y0, y1));
            oh[2*j + 1] = __float22half2_rn(make_float2(y2, y3));
        }
        orow[c] = out;
    }
}

// ======================= persistent fp16 HMMA GEMM (64x64 warp tiles) =======================
// out[m, n] = sum_k A[m,k] * Wt[n,k]  (+bias[n]) (+resid[m,n])
template <bool RESID, bool OUTH>
__global__ void __launch_bounds__(256, 1) hgemm_kernel(
    const __half* __restrict__ A,
    const __half* __restrict__ W,
    const float* __restrict__ bias,
    const float* __restrict__ resid,
    float* __restrict__ outf,
    __half* __restrict__ outh)
{
    extern __shared__ char smem_raw[];
    const uint32_t sbase = smem_u32(smem_raw);

    const int tid  = threadIdx.x;
    const int lane = tid & 31, wid = tid >> 5;
    const int warp_m = wid & 3;        // rows: warp_m*64  (BM=256)
    const int warp_n = wid >> 2;       // cols: warp_n*64  (BN=128)

    const int bid = blockIdx.x;
    const int G   = gridDim.x;
    const int my_ntiles = (NTILES - bid + G - 1) / G;
    const int total_gc  = my_ntiles * CHUNKS;

    const int lrow = tid >> 3;         // 0..31
    const int lkc  = tid & 7;          // 0..7

    float acc[4][8][4];
    #pragma unroll
    for (int mt = 0; mt < 4; mt++)
        #pragma unroll
        for (int nt = 0; nt < 8; nt++)
            #pragma unroll
            for (int i = 0; i < 4; i++) acc[mt][nt][i] = 0.0f;

    auto load_stage = [&](int gc) {
        const int t  = bid + (gc >> 5) * G;
        const int m0 = (t >> 4) * BM;
        const int n0 = (t & 15) * BN;
        const int k  = (gc & 31) * BK + lkc * 8;
        const uint32_t st = sbase + (uint32_t)(gc % NSTAGE) * STAGE_BYTES;
        #pragma unroll
        for (int i = 0; i < 8; i++) {
            const int row = lrow + i * 32;
            cp16(st + OFF_A + swz(row, lkc), A + (size_t)(m0 + row) * CH + k);
        }
        #pragma unroll
        for (int i = 0; i < 4; i++) {
            const int row = lrow + i * 32;
            cp16(st + OFF_W + swz(row, lkc), W + (size_t)(n0 + row) * CH + k);
        }
        CP_COMMIT();
    };

    auto compute_stage = [&](int gc) {
        const uint32_t st = sbase + (uint32_t)(gc % NSTAGE) * STAGE_BYTES;
        #pragma unroll
        for (int ks = 0; ks < BK / 16; ks++) {
            uint32_t af[4][4];
            {
                const int r = warp_m * 64 + (lane & 15);
                const int kc = ks * 2 + (lane >> 4);
                #pragma unroll
                for (int mt = 0; mt < 4; mt++)
                    LDSM4(af[mt], st + OFF_A + swz(r + mt * 16, kc));
            }
            uint32_t bf[8][2];
            {
                const int rb = warp_n * 64 + ((lane >> 4) & 1) * 8 + (lane & 7);
                const int kc = ks * 2 + ((lane >> 3) & 1);
                #pragma unroll
                for (int p = 0; p < 4; p++) {
                    uint32_t r4[4];
                    LDSM4(r4, st + OFF_W + swz(rb + p * 16, kc));
                    bf[2*p][0]   = r4[0]; bf[2*p][1]   = r4[1];
                    bf[2*p+1][0] = r4[2]; bf[2*p+1][1] = r4[3];
                }
            }
            #pragma unroll
            for (int mt = 0; mt < 4; mt++)
                #pragma unroll
                for (int nt = 0; nt < 8; nt++)
                    MMA16816(acc[mt][nt], af[mt], bf[nt]);
        }
    };

    auto epilogue = [&](int t) {
        const int m0 = (t >> 4) * BM;
        const int n0 = (t & 15) * BN;
        #pragma unroll
        for (int mt = 0; mt < 4; mt++) {
            const int r0 = m0 + warp_m * 64 + mt * 16 + (lane >> 2);
            #pragma unroll
            for (int nt = 0; nt < 8; nt++) {
                const int col = n0 + warp_n * 64 + nt * 8 + (lane & 3) * 2;
                const float bx = __ldg(&bias[col]);
                const float by = __ldg(&bias[col + 1]);
                float2 v0 = make_float2(acc[mt][nt][0] + bx, acc[mt][nt][1] + by);
                float2 v1 = make_float2(acc[mt][nt][2] + bx, acc[mt][nt][3] + by);
                if constexpr (OUTH) {
                    *(__half2*)(outh + (size_t)r0 * CH + col)       = __float22half2_rn(v0);
                    *(__half2*)(outh + (size_t)(r0 + 8) * CH + col) = __float22half2_rn(v1);
                } else {
                    if constexpr (RESID) {
                        float2 ra = *(const float2*)(resid + (size_t)r0 * CH + col);
                        float2 rb = *(const float2*)(resid + (size_t)(r0 + 8) * CH + col);
                        v0.x += ra.x; v0.y += ra.y;
                        v1.x += rb.x; v1.y += rb.y;
                    }
                    *(float2*)(outf + (size_t)r0 * CH + col)       = v0;
                    *(float2*)(outf + (size_t)(r0 + 8) * CH + col) = v1;
                }
                acc[mt][nt][0] = 0.f; acc[mt][nt][1] = 0.f;
                acc[mt][nt][2] = 0.f; acc[mt][nt][3] = 0.f;
            }
        }
    };

    if (total_gc <= 0) return;
    load_stage(0);
    if (1 < total_gc) load_stage(1);
    if (2 < total_gc) load_stage(2);

    #pragma unroll 1
    for (int gc = 0; gc < total_gc; gc++) {
        CP_WAIT(2);
        __syncthreads();
        compute_stage(gc);
        if (gc + 3 < total_gc) load_stage(gc + 3);
        if ((gc & 31) == 31) epilogue(bid + (gc >> 5) * G);
    }
}

// ======================= host =======================
extern "C" void kernel_launch(void* const* d_in, const int* in_sizes, int n_in,
                              void* d_out, int out_size)
{
    const float* x   = (const float*)d_in[0];
    const float* w1  = (const float*)d_in[1];
    const float* b1  = (const float*)d_in[2];
    const float* w2  = (const float*)d_in[3];
    const float* b2  = (const float*)d_in[4];
    const float* g1  = (const float*)d_in[5];
    const float* be1 = (const float*)d_in[6];
    const float* g2  = (const float*)d_in[7];
    const float* be2 = (const float*)d_in[8];
    float* out = (float*)d_out;

    void* p;
    cudaGetSymbolAddress(&p, g_act); __half* act = (__half*)p;
    cudaGetSymbolAddress(&p, g_h1);  __half* h1 = (__half*)p;
    cudaGetSymbolAddress(&p, g_w1t); __half* w1t = (__half*)p;
    cudaGetSymbolAddress(&p, g_w2t); __half* w2t = (__half*)p;

    int nsm = 148;
    cudaDeviceGetAttribute(&nsm, cudaDevAttrMultiProcessorCount, 0);

    cudaFuncSetAttribute((const void*)hgemm_kernel<false, true>,
                         cudaFuncAttributeMaxDynamicSharedMemorySize, SMEM_TOTAL);
    cudaFuncSetAttribute((const void*)hgemm_kernel<true, false>,
                         cudaFuncAttributeMaxDynamicSharedMemorySize, SMEM_TOTAL);
    cudaFuncSetAttribute((const void*)preprocess_kernel,
                         cudaFuncAttributeMaxDynamicSharedMemorySize, PRE_SMEM);
    cudaFuncSetAttribute((const void*)ln_silu_f16_kernel,
                         cudaFuncAttributeMaxDynamicSharedMemorySize, LN2_SMEM);

    preprocess_kernel<<<8192 + ROWS / 8, 256, PRE_SMEM>>>(x, w1, w2, g1, be1, w1t, w2t, act);
    hgemm_kernel<false, true><<<nsm, 256, SMEM_TOTAL>>>(act, w1t, b1, nullptr, nullptr, h1);
    ln_silu_f16_kernel<<<ROWS / 8, 256, LN2_SMEM>>>(h1, g2, be2, act);
    hgemm_kernel<true, false><<<nsm, 256, SMEM_TOTAL>>>(act, w2t, b2, x, out, nullptr);
}

// round 17
// speedup vs baseline: 1.0760x; 1.0760x over previous
#include <cuda_runtime.h>
#include <cuda_fp16.h>
#include <stdint.h>
#include <math.h>

#define ROWS   (8 * 4096)     // 32768
#define CH     2048
#define BM     256
#define BN     128
#define BK     64
#define CHUNKS (CH / BK)      // 32 per tile
#define NSTAGE 4
#define NT_N   (CH / BN)      // 16
#define NT_M   (ROWS / BM)    // 128
#define NTILES (NT_M * NT_N)  // 2048

// per stage: A [256][64] half (32KB) + W [128][64] half (16KB)
#define A_BYTES     (256 * 64 * 2)
#define W_BYTES     (128 * 64 * 2)
#define OFF_A       0
#define OFF_W       (A_BYTES)
#define STAGE_BYTES (A_BYTES + W_BYTES)      // 48KB
#define SMEM_TOTAL  (NSTAGE * STAGE_BYTES)   // 192KB

// ---- scratch (__device__ globals; allocation-free rule) ----
__device__ __half g_act[(size_t)ROWS * CH];
__device__ __half g_h1 [(size_t)ROWS * CH];
__device__ __half g_w1t[(size_t)CH * CH];
__device__ __half g_w2t[(size_t)CH * CH];

// ======================= PTX helpers =======================
__device__ __forceinline__ uint32_t smem_u32(const void* p) {
    uint32_t a;
    asm("{ .reg .u64 t; cvta.to.shared.u64 t, %1; cvt.u32.u64 %0, t; }" : "=r"(a) : "l"(p));
    return a;
}

__device__ __forceinline__ void cp16(uint32_t s, const void* g) {
    asm volatile("cp.async.cg.shared.global [%0], [%1], 16;" :: "r"(s), "l"(g));
}

#define CP_COMMIT()   asm volatile("cp.async.commit_group;" ::: "memory")
#define CP_WAIT(n)    asm volatile("cp.async.wait_group %0;" :: "n"(n) : "memory")

#define LDSM4(r, addr) \
    asm volatile("ldmatrix.sync.aligned.m8n8.x4.shared.b16 {%0,%1,%2,%3}, [%4];" \
        : "=r"((r)[0]), "=r"((r)[1]), "=r"((r)[2]), "=r"((r)[3]) : "r"(addr))

#define MMA16816(c, a, b) \
    asm volatile("mma.sync.aligned.m16n8k16.row.col.f32.f16.f16.f32 " \
        "{%0,%1,%2,%3}, {%4,%5,%6,%7}, {%8,%9}, {%0,%1,%2,%3};" \
        : "+f"((c)[0]), "+f"((c)[1]), "+f"((c)[2]), "+f"((c)[3]) \
        : "r"((a)[0]), "r"((a)[1]), "r"((a)[2]), "r"((a)[3]), "r"((b)[0]), "r"((b)[1]))

// swizzled smem byte offset for (row, 16B-chunk kc) in a [rows][64]half matrix
__device__ __forceinline__ uint32_t swz(int row, int kc) {
    return (uint32_t)(row * 128 + ((kc ^ (row & 7)) << 4));
}

__device__ __forceinline__ float2 warp_reduce_sum2(float a, float b) {
    #pragma unroll
    for (int off = 16; off > 0; off >>= 1) {
        a += __shfl_xor_sync(0xffffffffu, a, off);
        b += __shfl_xor_sync(0xffffffffu, b, off);
    }
    return make_float2(a, b);
}

// ======================= fused preprocessing =======================
// blocks [0, 4096):           transpose+convert w1 -> w1t
// blocks [4096, 8192):        transpose+convert w2 -> w2t
// blocks [8192, 8192+ROWS/8): LN+SiLU, warp-per-row (two-pass), x -> act (fp16)
__global__ void __launch_bounds__(256) preprocess_kernel(
    const float* __restrict__ x,
    const float* __restrict__ w1,
    const float* __restrict__ w2,
    const float* __restrict__ gamma,
    const float* __restrict__ beta,
    __half* __restrict__ w1t,
    __half* __restrict__ w2t,
    __half* __restrict__ act)
{
    __shared__ float t[32][33];
    const int bid = blockIdx.x;
    const int tid = threadIdx.x;

    if (bid < 8192) {
        const float* w = (bid < 4096) ? w1 : w2;
        __half* wt     = (bid < 4096) ? w1t : w2t;
        const int b    = bid & 4095;
        const int n0   = (b & 63) * 32;
        const int k0   = (b >> 6) * 32;
        const int tx = tid & 31, ty = tid >> 5;
        for (int i = ty; i < 32; i += 8)
            t[i][tx] = w[(size_t)(k0 + i) * CH + n0 + tx];
        __syncthreads();
        for (int i = ty; i < 32; i += 8)
            wt[(size_t)(n0 + i) * CH + k0 + tx] = __float2half_rn(t[tx][i]);
        return;
    }

    // warp-per-row LN+SiLU, two-pass (fp32 in, fp16 out)
    const size_t row = (size_t)(bid - 8192) * 8 + (tid >> 5);
    const int lane = tid & 31;
    const float4* xr = (const float4*)(x + row * (size_t)CH);   // 512 float4 per row

    // pass 1: stream + accumulate (no data kept live)
    float s = 0.f, sq = 0.f;
    #pragma unroll
    for (int i = 0; i < 16; i++) {
        float4 v = xr[lane + i * 32];
        s  += v.x + v.y + v.z + v.w;
        sq += v.x*v.x + v.y*v.y + v.z*v.z + v.w*v.w;
    }
    float2 r = warp_reduce_sum2(s, sq);
    const float inv_n = 1.0f / (float)CH;
    float mu  = r.x * inv_n;
    float var = r.y * inv_n - mu * mu;
    float inv = rsqrtf(var + 1e-6f);

    // launder pointer: stop compiler merging pass2 loads with pass1
    const float4* xr2 = xr;
    asm("" : "+l"(xr2));

    const float4* gr = (const float4*)gamma;
    const float4* br = (const float4*)beta;
    uint2* orow = (uint2*)(act + row * (size_t)CH);   // 512 uint2 per row
    #pragma unroll
    for (int i = 0; i < 16; i++) {
        const int c = lane + i * 32;
        float4 v = xr2[c];                 // L2-hot reload
        float4 g = gr[c], b = br[c];
        float y0 = (v.x - mu) * inv * g.x + b.x;
        float y1 = (v.y - mu) * inv * g.y + b.y;
        float y2 = (v.z - mu) * inv * g.z + b.z;
        float y3 = (v.w - mu) * inv * g.w + b.w;
        y0 *= 1.0f / (1.0f + __expf(-y0));
        y1 *= 1.0f / (1.0f + __expf(-y1));
        y2 *= 1.0f / (1.0f + __expf(-y2));
        y3 *= 1.0f / (1.0f + __expf(-y3));
        __half2 h0 = __float22half2_rn(make_float2(y0, y1));
        __half2 h1v = __float22half2_rn(make_float2(y2, y3));
        uint2 o;
        o.x = *(uint32_t*)&h0;
        o.y = *(uint32_t*)&h1v;
        orow[c] = o;
    }
}

// ======================= LN + SiLU (fp16 in, warp-per-row two-pass) -> fp16 =======================
__global__ void __launch_bounds__(256) ln_silu_f16_kernel(
    const __half* __restrict__ x,
    const float* __restrict__ gamma,
    const float* __restrict__ beta,
    __half* __restrict__ o)
{
    const size_t row = (size_t)blockIdx.x * 8 + (threadIdx.x >> 5);
    const int lane = threadIdx.x & 31;
    const uint4* xr = (const uint4*)(x + row * (size_t)CH);   // 256 uint4 per row (8 halfs each)

    float s = 0.f, sq = 0.f;
    #pragma unroll
    for (int i = 0; i < 8; i++) {
        uint4 raw = xr[lane + i * 32];
        const __half2* h = (const __half2*)&raw;
        #pragma unroll
        for (int j = 0; j < 4; j++) {
            float2 f = __half22float2(h[j]);
            s += f.x + f.y;
            sq += f.x*f.x + f.y*f.y;
        }
    }
    float2 r = warp_reduce_sum2(s, sq);
    const float inv_n = 1.0f / (float)CH;
    float mu  = r.x * inv_n;
    float var = r.y * inv_n - mu * mu;
    float inv = rsqrtf(var + 1e-6f);

    const uint4* xr2 = xr;
    asm("" : "+l"(xr2));

    const float4* gr = (const float4*)gamma;
    const float4* br = (const float4*)beta;
    uint4* orow = (uint4*)(o + row * (size_t)CH);
    #pragma unroll
    for (int i = 0; i < 8; i++) {
        const int c = lane + i * 32;         // uint4 index; covers elems 8c..8c+7
        uint4 raw = xr2[c];                  // L2-hot reload
        const __half2* h = (const __half2*)&raw;
        uint4 out;
        __half2* oh = (__half2*)&out;
        #pragma unroll
        for (int j = 0; j < 2; j++) {
            float4 g = gr[2*c + j], b = br[2*c + j];
            float2 f0 = __half22float2(h[2*j]);
            float2 f1 = __half22float2(h[2*j + 1]);
            float y0 = (f0.x - mu) * inv * g.x + b.x;
            float y1 = (f0.y - mu) * inv * g.y + b.y;
            float y2 = (f1.x - mu) * inv * g.z + b.z;
            float y3 = (f1.y - mu) * inv * g.w + b.w;
            y0 *= 1.0f / (1.0f + __expf(-y0));
            y1 *= 1.0f / (1.0f + __expf(-y1));
            y2 *= 1.0f / (1.0f + __expf(-y2));
            y3 *= 1.0f / (1.0f + __expf(-y3));
            oh[2*j]     = __float22half2_rn(make_float2(y0, y1));
            oh[2*j + 1] = __float22half2_rn(make_float2(y2, y3));
        }
        orow[c] = out;
    }
}

// ======================= persistent fp16 HMMA GEMM (64x64 warp tiles) =======================
// out[m, n] = sum_k A[m,k] * Wt[n,k]  (+bias[n]) (+resid[m,n])
template <bool RESID, bool OUTH>
__global__ void __launch_bounds__(256, 1) hgemm_kernel(
    const __half* __restrict__ A,
    const __half* __restrict__ W,
    const float* __restrict__ bias,
    const float* __restrict__ resid,
    float* __restrict__ outf,
    __half* __restrict__ outh)
{
    extern __shared__ char smem_raw[];
    const uint32_t sbase = smem_u32(smem_raw);

    const int tid  = threadIdx.x;
    const int lane = tid & 31, wid = tid >> 5;
    const int warp_m = wid & 3;        // rows: warp_m*64  (BM=256)
    const int warp_n = wid >> 2;       // cols: warp_n*64  (BN=128)

    const int bid = blockIdx.x;
    const int G   = gridDim.x;
    const int my_ntiles = (NTILES - bid + G - 1) / G;
    const int total_gc  = my_ntiles * CHUNKS;

    const int lrow = tid >> 3;         // 0..31
    const int lkc  = tid & 7;          // 0..7

    float acc[4][8][4];
    #pragma unroll
    for (int mt = 0; mt < 4; mt++)
        #pragma unroll
        for (int nt = 0; nt < 8; nt++)
            #pragma unroll
            for (int i = 0; i < 4; i++) acc[mt][nt][i] = 0.0f;

    auto load_stage = [&](int gc) {
        const int t  = bid + (gc >> 5) * G;
        const int m0 = (t >> 4) * BM;
        const int n0 = (t & 15) * BN;
        const int k  = (gc & 31) * BK + lkc * 8;
        const uint32_t st = sbase + (uint32_t)(gc % NSTAGE) * STAGE_BYTES;
        #pragma unroll
        for (int i = 0; i < 8; i++) {
            const int row = lrow + i * 32;
            cp16(st + OFF_A + swz(row, lkc), A + (size_t)(m0 + row) * CH + k);
        }
        #pragma unroll
        for (int i = 0; i < 4; i++) {
            const int row = lrow + i * 32;
            cp16(st + OFF_W + swz(row, lkc), W + (size_t)(n0 + row) * CH + k);
        }
        CP_COMMIT();
    };

    auto compute_stage = [&](int gc) {
        const uint32_t st = sbase + (uint32_t)(gc % NSTAGE) * STAGE_BYTES;
        #pragma unroll
        for (int ks = 0; ks < BK / 16; ks++) {
            uint32_t af[4][4];
            {
                const int r = warp_m * 64 + (lane & 15);
                const int kc = ks * 2 + (lane >> 4);
                #pragma unroll
                for (int mt = 0; mt < 4; mt++)
                    LDSM4(af[mt], st + OFF_A + swz(r + mt * 16, kc));
            }
            uint32_t bf[8][2];
            {
                const int rb = warp_n * 64 + ((lane >> 4) & 1) * 8 + (lane & 7);
                const int kc = ks * 2 + ((lane >> 3) & 1);
                #pragma unroll
                for (int p = 0; p < 4; p++) {
                    uint32_t r4[4];
                    LDSM4(r4, st + OFF_W + swz(rb + p * 16, kc));
                    bf[2*p][0]   = r4[0]; bf[2*p][1]   = r4[1];
                    bf[2*p+1][0] = r4[2]; bf[2*p+1][1] = r4[3];
                }
            }
            #pragma unroll
            for (int mt = 0; mt < 4; mt++)
                #pragma unroll
                for (int nt = 0; nt < 8; nt++)
                    MMA16816(acc[mt][nt], af[mt], bf[nt]);
        }
    };

    auto epilogue = [&](int t) {
        const int m0 = (t >> 4) * BM;
        const int n0 = (t & 15) * BN;
        #pragma unroll
        for (int mt = 0; mt < 4; mt++) {
            const int r0 = m0 + warp_m * 64 + mt * 16 + (lane >> 2);
            #pragma unroll
            for (int nt = 0; nt < 8; nt++) {
                const int col = n0 + warp_n * 64 + nt * 8 + (lane & 3) * 2;
                const float bx = __ldg(&bias[col]);
                const float by = __ldg(&bias[col + 1]);
                float2 v0 = make_float2(acc[mt][nt][0] + bx, acc[mt][nt][1] + by);
                float2 v1 = make_float2(acc[mt][nt][2] + bx, acc[mt][nt][3] + by);
                if constexpr (OUTH) {
                    *(__half2*)(outh + (size_t)r0 * CH + col)       = __float22half2_rn(v0);
                    *(__half2*)(outh + (size_t)(r0 + 8) * CH + col) = __float22half2_rn(v1);
                } else {
                    if constexpr (RESID) {
                        float2 ra = *(const float2*)(resid + (size_t)r0 * CH + col);
                        float2 rb = *(const float2*)(resid + (size_t)(r0 + 8) * CH + col);
                        v0.x += ra.x; v0.y += ra.y;
                        v1.x += rb.x; v1.y += rb.y;
                    }
                    *(float2*)(outf + (size_t)r0 * CH + col)       = v0;
                    *(float2*)(outf + (size_t)(r0 + 8) * CH + col) = v1;
                }
                acc[mt][nt][0] = 0.f; acc[mt][nt][1] = 0.f;
                acc[mt][nt][2] = 0.f; acc[mt][nt][3] = 0.f;
            }
        }
    };

    if (total_gc <= 0) return;
    load_stage(0);
    if (1 < total_gc) load_stage(1);
    if (2 < total_gc) load_stage(2);

    #pragma unroll 1
    for (int gc = 0; gc < total_gc; gc++) {
        CP_WAIT(2);
        __syncthreads();
        compute_stage(gc);
        if (gc + 3 < total_gc) load_stage(gc + 3);
        if ((gc & 31) == 31) epilogue(bid + (gc >> 5) * G);
    }
}

// ======================= host =======================
extern "C" void kernel_launch(void* const* d_in, const int* in_sizes, int n_in,
                              void* d_out, int out_size)
{
    const float* x   = (const float*)d_in[0];
    const float* w1  = (const float*)d_in[1];
    const float* b1  = (const float*)d_in[2];
    const float* w2  = (const float*)d_in[3];
    const float* b2  = (const float*)d_in[4];
    const float* g1  = (const float*)d_in[5];
    const float* be1 = (const float*)d_in[6];
    const float* g2  = (const float*)d_in[7];
    const float* be2 = (const float*)d_in[8];
    float* out = (float*)d_out;

    void* p;
    cudaGetSymbolAddress(&p, g_act); __half* act = (__half*)p;
    cudaGetSymbolAddress(&p, g_h1);  __half* h1 = (__half*)p;
    cudaGetSymbolAddress(&p, g_w1t); __half* w1t = (__half*)p;
    cudaGetSymbolAddress(&p, g_w2t); __half* w2t = (__half*)p;

    int nsm = 148;
    cudaDeviceGetAttribute(&nsm, cudaDevAttrMultiProcessorCount, 0);

    cudaFuncSetAttribute((const void*)hgemm_kernel<false, true>,
                         cudaFuncAttributeMaxDynamicSharedMemorySize, SMEM_TOTAL);
    cudaFuncSetAttribute((const void*)hgemm_kernel<true, false>,
                         cudaFuncAttributeMaxDynamicSharedMemorySize, SMEM_TOTAL);

    preprocess_kernel<<<8192 + ROWS / 8, 256>>>(x, w1, w2, g1, be1, w1t, w2t, act);
    hgemm_kernel<false, true><<<nsm, 256, SMEM_TOTAL>>>(act, w1t, b1, nullptr, nullptr, h1);
    ln_silu_f16_kernel<<<ROWS / 8, 256>>>(h1, g2, be2, act);
    hgemm_kernel<true, false><<<nsm, 256, SMEM_TOTAL>>>(act, w2t, b2, x, out, nullptr);
}